// round 16
// baseline (speedup 1.0000x reference)
#include <cuda_runtime.h>
#include <math.h>

// Problem constants (fixed by setup_inputs)
#define DIM   384
#define HID   1536
#define BATCH 16
#define SEQ   2048
#define ROWS  (BATCH*SEQ)   // 32768

// ---------------- scratch (device globals; no allocation allowed) -----------
__device__ __align__(16) float g_h1[ROWS*DIM];
__device__ __align__(16) float g_h2[ROWS*DIM];
__device__ __align__(16) float g_q [ROWS*DIM];
__device__ __align__(16) float g_k [ROWS*DIM];
__device__ __align__(16) float g_v [ROWS*DIM];
__device__ __align__(16) float g_av[ROWS*DIM];
__device__ __align__(16) float g_h3[ROWS*DIM];
__device__ __align__(16) float g_s [(size_t)BATCH*SEQ*SEQ];   // 268 MB scores
__device__ __align__(16) float g_ff[(size_t)ROWS*HID];        // 201 MB MLP hidden

// ---------------- packed f32x2 helpers (Blackwell FFMA2 path) ---------------
__device__ __forceinline__ unsigned long long pack2(float x) {
    unsigned long long r;
    asm("mov.b64 %0, {%1, %2};" : "=l"(r) : "f"(x), "f"(x));
    return r;
}
__device__ __forceinline__ unsigned long long fma2(unsigned long long a,
                                                   unsigned long long b,
                                                   unsigned long long c) {
    unsigned long long d;
    asm("fma.rn.f32x2 %0, %1, %2, %3;" : "=l"(d) : "l"(a), "l"(b), "l"(c));
    return d;
}
__device__ __forceinline__ float2 unpack2(unsigned long long v) {
    float lo, hi;
    asm("mov.b64 {%0, %1}, %2;" : "=f"(lo), "=f"(hi) : "l"(v));
    return make_float2(lo, hi);
}

// ---------------- LayerNorm: one 128-thread block per 384-wide row ----------
__global__ void ln_kernel(const float* __restrict__ x, const float* __restrict__ g,
                          const float* __restrict__ b, float* __restrict__ o) {
    __shared__ float2 red[4];
    const int row = blockIdx.x;
    const int tid = threadIdx.x;
    const float* xr = x + (long long)row * DIM;

    float v0 = xr[tid], v1 = xr[tid + 128], v2 = xr[tid + 256];
    float s = v0 + v1 + v2;
    float q = v0*v0 + v1*v1 + v2*v2;
    #pragma unroll
    for (int off = 16; off > 0; off >>= 1) {
        s += __shfl_down_sync(0xffffffffu, s, off);
        q += __shfl_down_sync(0xffffffffu, q, off);
    }
    if ((tid & 31) == 0) red[tid >> 5] = make_float2(s, q);
    __syncthreads();
    float S = red[0].x + red[1].x + red[2].x + red[3].x;
    float Q = red[0].y + red[1].y + red[2].y + red[3].y;
    const float mu  = S * (1.0f / DIM);
    const float var = Q * (1.0f / DIM) - mu * mu;
    const float inv = rsqrtf(var + 1e-5f);

    float* orow = o + (long long)row * DIM;
    orow[tid]       = (v0 - mu) * inv * g[tid]       + b[tid];
    orow[tid + 128] = (v1 - mu) * inv * g[tid + 128] + b[tid + 128];
    orow[tid + 256] = (v2 - mu) * inv * g[tid + 256] + b[tid + 256];
}

// ---------------- row softmax over 2048 keys, in place ----------------------
__global__ void softmax_kernel(float* __restrict__ s) {
    __shared__ float red[8];
    const long long row = blockIdx.x;
    float* p = s + row * (long long)SEQ;
    const int tid = threadIdx.x;

    float v[8];
    float mx = -1e30f;
    #pragma unroll
    for (int j = 0; j < 8; j++) { v[j] = p[tid + j * 256]; mx = fmaxf(mx, v[j]); }
    #pragma unroll
    for (int off = 16; off > 0; off >>= 1) mx = fmaxf(mx, __shfl_xor_sync(0xffffffffu, mx, off));
    if ((tid & 31) == 0) red[tid >> 5] = mx;
    __syncthreads();
    mx = red[0];
    #pragma unroll
    for (int i = 1; i < 8; i++) mx = fmaxf(mx, red[i]);

    float sum = 0.0f;
    #pragma unroll
    for (int j = 0; j < 8; j++) { v[j] = __expf(v[j] - mx); sum += v[j]; }
    #pragma unroll
    for (int off = 16; off > 0; off >>= 1) sum += __shfl_xor_sync(0xffffffffu, sum, off);
    __syncthreads();                 // done reading red as maxes
    if ((tid & 31) == 0) red[tid >> 5] = sum;
    __syncthreads();
    float tot = 0.0f;
    #pragma unroll
    for (int i = 0; i < 8; i++) tot += red[i];
    const float inv = 1.0f / tot;
    #pragma unroll
    for (int j = 0; j < 8; j++) p[tid + j * 256] = v[j] * inv;
}

// ---------------- generic fp32 GEMM, 128x128x16 tile, f32x2 inner loop ------
// C[z] = epilogue( alpha * A[z] @ B[z](^T) + bias )  (+ res)
// A: [M,K] row-major.  TRANSB ? B:[N,K] : B:[K,N].  All dims % tile == 0.
// res/C may alias element-wise (in-place residual) -> no __restrict__ on them.
template<bool TRANSB, bool GELU>
__global__ void __launch_bounds__(256, 2) gemm_kernel(
    const float* __restrict__ A, const float* __restrict__ B,
    const float* __restrict__ bias, const float* res, float* C,
    int N, int K,
    long long sA, long long sB, long long sC, float alpha)
{
    __shared__ __align__(16) float sAm[16 * 128];
    __shared__ __align__(16) float sBm[16 * 128];

    const int z = blockIdx.z;
    A += (long long)z * sA;
    B += (long long)z * sB;
    C += (long long)z * sC;
    if (res) res += (long long)z * sC;

    const int m0 = blockIdx.y * 128;
    const int n0 = blockIdx.x * 128;
    const int tid = threadIdx.x;
    const int tx = tid & 15, ty = tid >> 4;
    const int ty8 = ty * 8, tx8 = tx * 8;

    unsigned long long acc[4][8];
    #pragma unroll
    for (int i = 0; i < 4; i++)
        #pragma unroll
        for (int j = 0; j < 8; j++) acc[i][j] = 0ull;

    for (int k0 = 0; k0 < K; k0 += 16) {
        // A tile -> sAm[kk][mm] (k-major in smem; m contiguous for free pairs)
        #pragma unroll
        for (int i = 0; i < 2; i++) {
            const int idx = tid + i * 256;
            const int kq = idx & 3, mm = idx >> 2;
            const float4 va = *(const float4*)(A + (long long)(m0 + mm) * K + k0 + kq * 4);
            sAm[(kq * 4 + 0) * 128 + mm] = va.x;
            sAm[(kq * 4 + 1) * 128 + mm] = va.y;
            sAm[(kq * 4 + 2) * 128 + mm] = va.z;
            sAm[(kq * 4 + 3) * 128 + mm] = va.w;
        }
        // B tile -> sBm[kk][nn]
        if (TRANSB) {
            #pragma unroll
            for (int i = 0; i < 2; i++) {
                const int idx = tid + i * 256;
                const int kq = idx & 3, nn = idx >> 2;
                const float4 vb = *(const float4*)(B + (long long)(n0 + nn) * K + k0 + kq * 4);
                sBm[(kq * 4 + 0) * 128 + nn] = vb.x;
                sBm[(kq * 4 + 1) * 128 + nn] = vb.y;
                sBm[(kq * 4 + 2) * 128 + nn] = vb.z;
                sBm[(kq * 4 + 3) * 128 + nn] = vb.w;
            }
        } else {
            #pragma unroll
            for (int i = 0; i < 2; i++) {
                const int idx = tid + i * 256;
                const int kk = idx >> 5, c4 = idx & 31;
                *(float4*)&sBm[kk * 128 + c4 * 4] =
                    *(const float4*)(B + (long long)(k0 + kk) * N + n0 + c4 * 4);
            }
        }
        __syncthreads();

        #pragma unroll
        for (int kk = 0; kk < 16; kk++) {
            const float* ap = &sAm[kk * 128 + ty8];
            const float* bp = &sBm[kk * 128 + tx8];
            const ulonglong2 a01 = *(const ulonglong2*)ap;        // rows +0/+1, +2/+3
            const ulonglong2 a23 = *(const ulonglong2*)(ap + 4);  // rows +4/+5, +6/+7
            const float4 b0 = *(const float4*)bp;
            const float4 b1 = *(const float4*)(bp + 4);
            const unsigned long long am[4] = { a01.x, a01.y, a23.x, a23.y };
            const unsigned long long bm[8] = {
                pack2(b0.x), pack2(b0.y), pack2(b0.z), pack2(b0.w),
                pack2(b1.x), pack2(b1.y), pack2(b1.z), pack2(b1.w)
            };
            #pragma unroll
            for (int mp = 0; mp < 4; mp++)
                #pragma unroll
                for (int n = 0; n < 8; n++)
                    acc[mp][n] = fma2(am[mp], bm[n], acc[mp][n]);
        }
        __syncthreads();
    }

    // ---------------- epilogue ----------------
    float bcol[8];
    #pragma unroll
    for (int n = 0; n < 8; n++) bcol[n] = bias ? bias[n0 + tx8 + n] : 0.0f;

    #pragma unroll
    for (int mp = 0; mp < 4; mp++) {
        float r0[8], r1[8];
        #pragma unroll
        for (int n = 0; n < 8; n++) {
            const float2 u = unpack2(acc[mp][n]);
            r0[n] = u.x; r1[n] = u.y;
        }
        #pragma unroll
        for (int h = 0; h < 2; h++) {
            const float* rr = h ? r1 : r0;
            const int row = m0 + ty8 + mp * 2 + h;
            const long long base = (long long)row * N + n0 + tx8;
            float ov[8];
            #pragma unroll
            for (int n = 0; n < 8; n++) {
                float vv = rr[n] * alpha + bcol[n];
                if (GELU) vv = 0.5f * vv * (1.0f + erff(vv * 0.70710678118654752f));
                if (res) vv += res[base + n];
                ov[n] = vv;
            }
            *(float4*)(C + base)     = make_float4(ov[0], ov[1], ov[2], ov[3]);
            *(float4*)(C + base + 4) = make_float4(ov[4], ov[5], ov[6], ov[7]);
        }
    }
}

// ---------------- host: 11 graph-capturable launches -------------------------
extern "C" void kernel_launch(void* const* d_in, const int* in_sizes, int n_in,
                              void* d_out, int out_size) {
    const float* x1    = (const float*)d_in[0];
    const float* x2    = (const float*)d_in[1];
    const float* ln1_g = (const float*)d_in[2];
    const float* ln1_b = (const float*)d_in[3];
    const float* ln2_g = (const float*)d_in[4];
    const float* ln2_b = (const float*)d_in[5];
    const float* Wq    = (const float*)d_in[6];
    const float* bq    = (const float*)d_in[7];
    const float* Wk    = (const float*)d_in[8];
    const float* bk    = (const float*)d_in[9];
    const float* Wv    = (const float*)d_in[10];
    const float* bv    = (const float*)d_in[11];
    const float* Wo    = (const float*)d_in[12];
    const float* bo    = (const float*)d_in[13];
    const float* ln3_g = (const float*)d_in[14];
    const float* ln3_b = (const float*)d_in[15];
    const float* W1    = (const float*)d_in[16];
    const float* b1    = (const float*)d_in[17];
    const float* W2    = (const float*)d_in[18];
    const float* b2    = (const float*)d_in[19];
    float* out = (float*)d_out;

    float *h1, *h2, *q, *k, *v, *av, *h3, *s, *ff;
    cudaGetSymbolAddress((void**)&h1, g_h1);
    cudaGetSymbolAddress((void**)&h2, g_h2);
    cudaGetSymbolAddress((void**)&q,  g_q);
    cudaGetSymbolAddress((void**)&k,  g_k);
    cudaGetSymbolAddress((void**)&v,  g_v);
    cudaGetSymbolAddress((void**)&av, g_av);
    cudaGetSymbolAddress((void**)&h3, g_h3);
    cudaGetSymbolAddress((void**)&s,  g_s);
    cudaGetSymbolAddress((void**)&ff, g_ff);

    const float inv_sqrt_d = 0.05103103630798288f;   // 1/sqrt(384)

    // LN1(x1) -> h1 ; LN2(x2) -> h2
    ln_kernel<<<ROWS, 128>>>(x1, ln1_g, ln1_b, h1);
    ln_kernel<<<ROWS, 128>>>(x2, ln2_g, ln2_b, h2);

    // Projections: q = h1@Wq+bq ; k = h2@Wk+bk ; v = h2@Wv+bv
    dim3 gp(DIM / 128, ROWS / 128, 1);
    gemm_kernel<false, false><<<gp, 256>>>(h1, Wq, bq, nullptr, q, DIM, DIM, 0, 0, 0, 1.0f);
    gemm_kernel<false, false><<<gp, 256>>>(h2, Wk, bk, nullptr, k, DIM, DIM, 0, 0, 0, 1.0f);
    gemm_kernel<false, false><<<gp, 256>>>(h2, Wv, bv, nullptr, v, DIM, DIM, 0, 0, 0, 1.0f);

    // scores[b] = (q[b] @ k[b]^T) / sqrt(d)
    dim3 gs(SEQ / 128, SEQ / 128, BATCH);
    gemm_kernel<true, false><<<gs, 256>>>(q, k, nullptr, nullptr, s, SEQ, DIM,
        (long long)SEQ * DIM, (long long)SEQ * DIM, (long long)SEQ * SEQ, inv_sqrt_d);

    // softmax over keys, in place
    softmax_kernel<<<ROWS, 256>>>(s);

    // av[b] = attn[b] @ v[b]
    dim3 ga(DIM / 128, SEQ / 128, BATCH);
    gemm_kernel<false, false><<<ga, 256>>>(s, v, nullptr, nullptr, av, DIM, SEQ,
        (long long)SEQ * SEQ, (long long)SEQ * DIM, (long long)SEQ * DIM, 1.0f);

    // x = x1 + av@Wo + bo   -> out
    gemm_kernel<false, false><<<gp, 256>>>(av, Wo, bo, x1, out, DIM, DIM, 0, 0, 0, 1.0f);

    // LN3(x) -> h3
    ln_kernel<<<ROWS, 128>>>(out, ln3_g, ln3_b, h3);

    // ff = gelu(h3@W1 + b1)
    dim3 g1(HID / 128, ROWS / 128, 1);
    gemm_kernel<false, true><<<g1, 256>>>(h3, W1, b1, nullptr, ff, HID, DIM, 0, 0, 0, 1.0f);

    // out = out + ff@W2 + b2   (in-place residual)
    gemm_kernel<false, false><<<gp, 256>>>(ff, W2, b2, out, out, DIM, HID, 0, 0, 0, 1.0f);
}